// round 16
// baseline (speedup 1.0000x reference)
#include <cuda_runtime.h>
#include <cuda_fp16.h>
#include <cuda_bf16.h>
#include <cstdint>

#define BB 4
#define SS 4096
#define DD 256
#define M_TOT (BB * SS)

// Scratch (device globals). Q pre-scaled by log2(e)/16; Vt is [b][d][s].
__device__ __half g_Q[M_TOT * DD];
__device__ __half g_K[M_TOT * DD];
__device__ __half g_Vt[M_TOT * DD];
__device__ __nv_bfloat16 g_Xh[M_TOT * DD], g_Xl[M_TOT * DD];     // attention out, split
__device__ __nv_bfloat16 g_WtH[4 * DD * DD], g_WtL[4 * DD * DD]; // W^T hi/lo, [n][k]

// ---------------- helpers ----------------
__device__ __forceinline__ uint32_t smem_u32(const void* p) {
    uint32_t a;
    asm("{ .reg .u64 t; cvta.to.shared.u64 t, %1; cvt.u32.u64 %0, t; }"
        : "=r"(a) : "l"(p));
    return a;
}
__device__ __forceinline__ uint32_t packh2(float a, float b) {
    __half2 v; v.x = __float2half(a); v.y = __float2half(b);
    return *reinterpret_cast<uint32_t*>(&v);
}
__device__ __forceinline__ uint32_t packb2(__nv_bfloat16 a, __nv_bfloat16 b) {
    __nv_bfloat162 v; v.x = a; v.y = b;
    return *reinterpret_cast<uint32_t*>(&v);
}
__device__ __forceinline__ void splitb(float x, __nv_bfloat16& h, __nv_bfloat16& l) {
    h = __float2bfloat16(x);
    l = __float2bfloat16(x - __bfloat162float(h));
}

#define LDSM4(d, addr) \
    asm volatile("ldmatrix.sync.aligned.m8n8.x4.shared.b16 {%0,%1,%2,%3}, [%4];" \
        : "=r"((d)[0]), "=r"((d)[1]), "=r"((d)[2]), "=r"((d)[3]) : "r"(addr))

#define MMAH(c, a, b0, b1) \
    asm volatile("mma.sync.aligned.m16n8k16.row.col.f32.f16.f16.f32 " \
        "{%0,%1,%2,%3}, {%4,%5,%6,%7}, {%8,%9}, {%0,%1,%2,%3};" \
        : "+f"((c)[0]), "+f"((c)[1]), "+f"((c)[2]), "+f"((c)[3]) \
        : "r"((a)[0]), "r"((a)[1]), "r"((a)[2]), "r"((a)[3]), "r"(b0), "r"(b1))

#define MMAB(c, a, b0, b1) \
    asm volatile("mma.sync.aligned.m16n8k16.row.col.f32.bf16.bf16.f32 " \
        "{%0,%1,%2,%3}, {%4,%5,%6,%7}, {%8,%9}, {%0,%1,%2,%3};" \
        : "+f"((c)[0]), "+f"((c)[1]), "+f"((c)[2]), "+f"((c)[3]) \
        : "r"((a)[0]), "r"((a)[1]), "r"((a)[2]), "r"((a)[3]), "r"(b0), "r"(b1))

#define CP_ASYNC16(dst, src) \
    asm volatile("cp.async.cg.shared.global [%0], [%1], 16;" \
                 :: "r"(dst), "l"(src) : "memory")
#define CP_COMMIT  asm volatile("cp.async.commit_group;" ::: "memory")
#define CP_WAIT0   asm volatile("cp.async.wait_group 0;" ::: "memory")

// ---------------- weight prep: W[k][n] f32 -> Wt[n][k] bf16 hi/lo ----------------
__global__ __launch_bounds__(256) void prep_w(
    const float* __restrict__ w0, const float* __restrict__ w1,
    const float* __restrict__ w2, const float* __restrict__ w3)
{
    const float* W = (blockIdx.z == 0) ? w0 : (blockIdx.z == 1) ? w1
                   : (blockIdx.z == 2) ? w2 : w3;
    __nv_bfloat16* TH = g_WtH + blockIdx.z * DD * DD;
    __nv_bfloat16* TL = g_WtL + blockIdx.z * DD * DD;

    __shared__ float t[32][33];
    const int tx = threadIdx.x & 31;
    const int ty = threadIdx.x >> 5;
    const int k0 = blockIdx.x * 32;
    const int n0 = blockIdx.y * 32;
#pragma unroll
    for (int i = 0; i < 4; i++)
        t[ty + 8 * i][tx] = W[(size_t)(k0 + ty + 8 * i) * DD + n0 + tx];
    __syncthreads();
#pragma unroll
    for (int i = 0; i < 4; i++) {
        float v = t[tx][ty + 8 * i];
        __nv_bfloat16 h, l; splitb(v, h, l);
        size_t idx = (size_t)(n0 + ty + 8 * i) * DD + k0 + tx;
        TH[idx] = h;
        TL[idx] = l;
    }
}

// ---------------- fused projection (split bf16, 3-MMA), grid = 128 (1 wave) ------
// (unchanged from R11/R14 — measured 28.7us QKV)
#define PP 528
#define A_H   0u
#define A_L   67584u
#define WBUF0 135168u
#define WBUF1 168960u
#define WLO   16896u
#define VT_OFF 202752u
#define PROJ_SMEM 219648

__global__ __launch_bounds__(256, 1) void proj_fused(
    const float* __restrict__ Af,
    const __nv_bfloat16* __restrict__ Xh, const __nv_bfloat16* __restrict__ Xl,
    const float* __restrict__ biasq, const float* __restrict__ biask,
    const float* __restrict__ biasv, const float* __restrict__ biaso,
    __half* __restrict__ Qo, __half* __restrict__ Ko, __half* __restrict__ Vo,
    float* __restrict__ Oo, int mode)
{
    extern __shared__ __align__(16) char sm[];
    const uint32_t sb = smem_u32(sm);
    const int tid  = threadIdx.x;
    const int wid  = tid >> 5;
    const int lane = tid & 31;
    const int row0 = blockIdx.x * 128;

    const int ntiles = (mode == 0) ? 24 : 8;
    const int wbase  = (mode == 0) ? 0 : 3;

    {
        const __nv_bfloat16* TH = g_WtH + (size_t)wbase * DD * DD;
        const __nv_bfloat16* TL = g_WtL + (size_t)wbase * DD * DD;
        const uint32_t wb = sb + WBUF0;
#pragma unroll
        for (int p = 0; p < 4; p++) {
            int idx = tid + p * 256;
            int rr = idx >> 5, c = idx & 31;
            CP_ASYNC16(wb + rr * PP + c * 16,       TH + (size_t)rr * DD + c * 8);
            CP_ASYNC16(wb + WLO + rr * PP + c * 16, TL + (size_t)rr * DD + c * 8);
        }
        CP_COMMIT;
    }

    const int lr  = lane & 7;
    const int lt2 = (lane >> 3) & 1;
    const int lt4 = lane >> 4;
    const uint32_t a_h = sb + A_H + (uint32_t)(wid * 16 + lt2 * 8 + lr) * PP + lt4 * 16;
    const uint32_t a_l = a_h + (A_L - A_H);
    const uint32_t bw_lane = (uint32_t)(lt4 * 8 + lr) * PP + lt2 * 16;
    const int g = lane >> 2, t = lane & 3;

#pragma unroll 1
    for (int tt = 0; tt < ntiles; tt++) {
        const int wt   = tt >> 3;
        const int col0 = (tt & 7) * 32;
        const int widx = wbase + wt;

        if ((tt & 7) == 0) {
            __syncthreads();
            if (mode == 0) {
                const int aoff = wt * 256;
#pragma unroll
                for (int p = 0; p < 32; p++) {
                    int idx = tid + p * 256;
                    int rr = idx >> 6, c4 = idx & 63;
                    float4 v = *(const float4*)&Af[(size_t)(row0 + rr) * 768 + aoff + c4 * 4];
                    __nv_bfloat16 h0, l0, h1, l1, h2, l2, h3, l3;
                    splitb(v.x, h0, l0); splitb(v.y, h1, l1);
                    splitb(v.z, h2, l2); splitb(v.w, h3, l3);
                    *(uint2*)(sm + A_H + rr * PP + c4 * 8) =
                        make_uint2(packb2(h0, h1), packb2(h2, h3));
                    *(uint2*)(sm + A_L + rr * PP + c4 * 8) =
                        make_uint2(packb2(l0, l1), packb2(l2, l3));
                }
            } else if (tt == 0) {
#pragma unroll
                for (int p = 0; p < 16; p++) {
                    int idx = tid + p * 256;
                    int rr = idx >> 5, c = idx & 31;
                    *(uint4*)(sm + A_H + rr * PP + c * 16) =
                        *(const uint4*)(Xh + (size_t)(row0 + rr) * DD + c * 8);
                    *(uint4*)(sm + A_L + rr * PP + c * 16) =
                        *(const uint4*)(Xl + (size_t)(row0 + rr) * DD + c * 8);
                }
            }
        }

        CP_WAIT0;
        __syncthreads();

        if (tt + 1 < ntiles) {
            const int wt1 = wbase + ((tt + 1) >> 3);
            const int co1 = ((tt + 1) & 7) * 32;
            const __nv_bfloat16* TH = g_WtH + (size_t)wt1 * DD * DD + (size_t)co1 * DD;
            const __nv_bfloat16* TL = g_WtL + (size_t)wt1 * DD * DD + (size_t)co1 * DD;
            const uint32_t wb = sb + (((tt + 1) & 1) ? WBUF1 : WBUF0);
#pragma unroll
            for (int p = 0; p < 4; p++) {
                int idx = tid + p * 256;
                int rr = idx >> 5, c = idx & 31;
                CP_ASYNC16(wb + rr * PP + c * 16,       TH + (size_t)rr * DD + c * 8);
                CP_ASYNC16(wb + WLO + rr * PP + c * 16, TL + (size_t)rr * DD + c * 8);
            }
            CP_COMMIT;
        }

        const uint32_t b_h = sb + ((tt & 1) ? WBUF1 : WBUF0) + bw_lane;
        const uint32_t b_l = b_h + WLO;
        float c_[4][4];
#pragma unroll
        for (int i = 0; i < 4; i++)
#pragma unroll
            for (int j = 0; j < 4; j++) c_[i][j] = 0.f;

#pragma unroll
        for (int ks = 0; ks < 16; ks++) {
            uint32_t ah[4], al[4];
            LDSM4(ah, a_h + ks * 32);
            LDSM4(al, a_l + ks * 32);
#pragma unroll
            for (int j2 = 0; j2 < 2; j2++) {
                uint32_t bh[4], bl[4];
                LDSM4(bh, b_h + j2 * (16 * PP) + ks * 32);
                LDSM4(bl, b_l + j2 * (16 * PP) + ks * 32);
                MMAB(c_[2 * j2],     ah, bh[0], bh[1]);
                MMAB(c_[2 * j2],     al, bh[0], bh[1]);
                MMAB(c_[2 * j2],     ah, bl[0], bl[1]);
                MMAB(c_[2 * j2 + 1], ah, bh[2], bh[3]);
                MMAB(c_[2 * j2 + 1], al, bh[2], bh[3]);
                MMAB(c_[2 * j2 + 1], ah, bl[2], bl[3]);
            }
        }

        if (widx == 0 || widx == 1) {
            __half* outp = (widx == 0) ? Qo : Ko;
            const float* bp = (widx == 0) ? biasq : biask;
            const float scale = (widx == 0) ? 0.0625f * 1.44269504088896f : 1.0f;
            const int r0 = row0 + wid * 16 + g;
#pragma unroll
            for (int nt = 0; nt < 4; nt++) {
                int col = col0 + nt * 8 + 2 * t;
                float b0 = bp[col], b1 = bp[col + 1];
                *(uint32_t*)&outp[(size_t)r0 * DD + col] =
                    packh2((c_[nt][0] + b0) * scale, (c_[nt][1] + b1) * scale);
                *(uint32_t*)&outp[(size_t)(r0 + 8) * DD + col] =
                    packh2((c_[nt][2] + b0) * scale, (c_[nt][3] + b1) * scale);
            }
        } else if (widx == 2) {
            __syncthreads();
            float* sh = (float*)(sm + VT_OFF);
            const int rl = wid * 16 + g;
#pragma unroll
            for (int nt = 0; nt < 4; nt++) {
                int cl = nt * 8 + 2 * t;
                float b0 = biasv[col0 + cl], b1 = biasv[col0 + cl + 1];
                sh[rl * 33 + cl]           = c_[nt][0] + b0;
                sh[rl * 33 + cl + 1]       = c_[nt][1] + b1;
                sh[(rl + 8) * 33 + cl]     = c_[nt][2] + b0;
                sh[(rl + 8) * 33 + cl + 1] = c_[nt][3] + b1;
            }
            __syncthreads();
            const int sl = tid & 63;
            const int d0 = tid >> 6;
            const int b_ = row0 >> 12;
            const int s0 = row0 & 4095;
            __half* Vb = Vo + (size_t)b_ * DD * SS;
#pragma unroll
            for (int dd = 0; dd < 8; dd++) {
                int d = d0 + dd * 4;
                *(uint32_t*)&Vb[(size_t)(col0 + d) * SS + s0 + 2 * sl] =
                    packh2(sh[(2 * sl) * 33 + d], sh[(2 * sl + 1) * 33 + d]);
            }
        } else {
            const int r0 = row0 + wid * 16 + g;
#pragma unroll
            for (int nt = 0; nt < 4; nt++) {
                int col = col0 + nt * 8 + 2 * t;
                float b0 = biaso[col], b1 = biaso[col + 1];
                *(float2*)&Oo[(size_t)r0 * DD + col] =
                    make_float2(c_[nt][0] + b0, c_[nt][1] + b1);
                *(float2*)&Oo[(size_t)(r0 + 8) * DD + col] =
                    make_float2(c_[nt][2] + b0, c_[nt][3] + b1);
            }
        }
    }
}

// ---------------- flash6: 64-row Q CTAs, KV tile 32, 2 CTAs/SM --------------------
// 8 warps: r = wid&3 (row group of 16), h = wid>>2 (half).
// S: warp computes 16 rows x 16 kv (its half).  PV: 16 rows x 128 D (its half), K=32;
// own-kv-half P stays in registers (C->A repack), other half read from smem.
// smem: Q 64x528=33792 | KV double buf: (K 32x528=16896 + V 256x80=20480)x2=74752
//       P 64x80=5120 | rsum 512   -> total 114176 (2 CTAs/SM: 228352 <= 228KB)
#define F6_QP   528
#define F6_VP   80
#define F6_Q    0u
#define F6_BUF0 33792u
#define F6_KSZ  16896u
#define F6_BUFSZ 37376u
#define F6_P    108544u
#define F6_RS   113664u
#define F6_SMEM 114176

__global__ void __launch_bounds__(256, 2) flash6_kernel()
{
    extern __shared__ __align__(16) char sm[];
    const uint32_t sb = smem_u32(sm);

    const int tid  = threadIdx.x;
    const int wid  = tid >> 5;
    const int lane = tid & 31;
    const int r    = wid & 3;
    const int h    = wid >> 2;
    const int b    = blockIdx.y;
    const int q0   = blockIdx.x * 64;

    const __half* Qg  = g_Q  + (size_t)(b * SS + q0) * DD;
    const __half* Kg  = g_K  + (size_t)b * SS * DD;
    const __half* Vtg = g_Vt + (size_t)b * DD * SS;

    // stage Q (64 x 256 fp16 = 2048 x 16B)
#pragma unroll
    for (int p = 0; p < 8; p++) {
        int idx = tid + p * 256;
        int rr = idx >> 5, c = idx & 31;
        *(uint4*)(sm + F6_Q + rr * F6_QP + c * 16) =
            *(const uint4*)(Qg + (size_t)rr * DD + c * 8);
    }
    // prefetch KV tile 0
    {
        const uint32_t kb = sb + F6_BUF0;
        const uint32_t vb = kb + F6_KSZ;
#pragma unroll
        for (int p = 0; p < 4; p++) {
            int idx = tid + p * 256;
            int rr = idx >> 5, c = idx & 31;
            CP_ASYNC16(kb + rr * F6_QP + c * 16, Kg + (size_t)rr * DD + c * 8);
        }
#pragma unroll
        for (int p = 0; p < 4; p++) {
            int idx = tid + p * 256;
            int d = idx >> 2, c = idx & 3;
            CP_ASYNC16(vb + d * F6_VP + c * 16, Vtg + (size_t)d * SS + c * 8);
        }
        CP_COMMIT;
    }

    const int lr  = lane & 7;
    const int lt2 = (lane >> 3) & 1;
    const int lt4 = lane >> 4;
    const int g   = lane >> 2, t = lane & 3;
    const uint32_t a_q = sb + F6_Q + (uint32_t)(r * 16 + lt2 * 8 + lr) * F6_QP + lt4 * 16;
    const uint32_t bk_lane = (uint32_t)(h * 16 + lt4 * 8 + lr) * F6_QP + lt2 * 16;
    const uint32_t bv_lane = (uint32_t)(h * 128 + lt4 * 8 + lr) * F6_VP + lt2 * 16;
    const uint32_t a_px = sb + F6_P + (uint32_t)(r * 16 + lt2 * 8 + lr) * F6_VP
                        + lt4 * 16 + (uint32_t)(1 - h) * 32;   // other-half A frag
    const uint32_t p_w  = sb + F6_P + (uint32_t)(r * 16 + g) * F6_VP
                        + (uint32_t)(h * 16 + 2 * t) * 2;      // own-half C store

    float o[64];
#pragma unroll
    for (int i = 0; i < 64; i++) o[i] = 0.f;
    float rs0 = 0.f, rs1 = 0.f;

#pragma unroll 1
    for (int kt = 0; kt < SS / 32; kt++) {
        const uint32_t base = sb + F6_BUF0 + (uint32_t)(kt & 1) * F6_BUFSZ;
        CP_WAIT0;
        __syncthreads();   // KV tile kt visible; prev tile's P reads done

        if (kt < SS / 32 - 1) {
            const uint32_t kb = sb + F6_BUF0 + (uint32_t)((kt + 1) & 1) * F6_BUFSZ;
            const uint32_t vb = kb + F6_KSZ;
            const __half* Kn = Kg  + (size_t)(kt + 1) * 32 * DD;
            const __half* Vn = Vtg + (size_t)(kt + 1) * 32;
#pragma unroll
            for (int p = 0; p < 4; p++) {
                int idx = tid + p * 256;
                int rr = idx >> 5, c = idx & 31;
                CP_ASYNC16(kb + rr * F6_QP + c * 16, Kn + (size_t)rr * DD + c * 8);
            }
#pragma unroll
            for (int p = 0; p < 4; p++) {
                int idx = tid + p * 256;
                int d = idx >> 2, c = idx & 3;
                CP_ASYNC16(vb + d * F6_VP + c * 16, Vn + (size_t)d * SS + c * 8);
            }
            CP_COMMIT;
        }

        // ---- S: 16 rows x 16 kv (own half), K=256 ----
        const uint32_t b_k = base + bk_lane;
        float s[2][4];
#pragma unroll
        for (int i = 0; i < 2; i++)
#pragma unroll
            for (int j = 0; j < 4; j++) s[i][j] = 0.f;

#pragma unroll
        for (int ks = 0; ks < 16; ks++) {
            uint32_t a[4], bb[4];
            LDSM4(a, a_q + ks * 32);
            LDSM4(bb, b_k + ks * 32);
            MMAH(s[0], a, bb[0], bb[1]);
            MMAH(s[1], a, bb[2], bb[3]);
        }

        // ---- exp2; own-half A-frag in regs; store own half P to smem ----
        float p0 = exp2f(s[0][0]), p1 = exp2f(s[0][1]);
        float p2 = exp2f(s[0][2]), p3 = exp2f(s[0][3]);
        float q0 = exp2f(s[1][0]), q1 = exp2f(s[1][1]);
        float q2 = exp2f(s[1][2]), q3 = exp2f(s[1][3]);
        rs0 += (p0 + p1) + (q0 + q1);
        rs1 += (p2 + p3) + (q2 + q3);
        uint32_t paO[4];
        paO[0] = packh2(p0, p1);
        paO[1] = packh2(p2, p3);
        paO[2] = packh2(q0, q1);
        paO[3] = packh2(q2, q3);
        *(uint32_t*)(sm + (p_w - sb))                 = paO[0];  // row g,   cols 2t..
        *(uint32_t*)(sm + (p_w - sb) + 8 * F6_VP)     = paO[1];  // row g+8
        *(uint32_t*)(sm + (p_w - sb) + 16)            = paO[2];  // row g,   cols 8+2t
        *(uint32_t*)(sm + (p_w - sb) + 8 * F6_VP + 16) = paO[3]; // row g+8
        __syncthreads();   // full P tile visible

        // ---- PV: 16 rows x 128 D (own half), K=32 ----
        const uint32_t b_v = base + F6_KSZ + bv_lane;
        uint32_t paX[4];
        LDSM4(paX, a_px);   // other kv-half A-frag
#pragma unroll
        for (int jj = 0; jj < 8; jj++) {
            uint32_t vv[4];
            LDSM4(vv, b_v + jj * (16 * F6_VP) + h * 32);
            MMAH(o + 8 * jj,     paO, vv[0], vv[1]);
            MMAH(o + 8 * jj + 4, paO, vv[2], vv[3]);
        }
#pragma unroll
        for (int jj = 0; jj < 8; jj++) {
            uint32_t vv[4];
            LDSM4(vv, b_v + jj * (16 * F6_VP) + (1 - h) * 32);
            MMAH(o + 8 * jj,     paX, vv[0], vv[1]);
            MMAH(o + 8 * jj + 4, paX, vv[2], vv[3]);
        }
    }

    // ---- combine row sums across halves ----
    rs0 += __shfl_xor_sync(0xffffffffu, rs0, 1);
    rs0 += __shfl_xor_sync(0xffffffffu, rs0, 2);
    rs1 += __shfl_xor_sync(0xffffffffu, rs1, 1);
    rs1 += __shfl_xor_sync(0xffffffffu, rs1, 2);
    float* rsum = (float*)(sm + F6_RS);
    if (t == 0) {
        rsum[h * 64 + r * 16 + g]     = rs0;
        rsum[h * 64 + r * 16 + g + 8] = rs1;
    }
    __syncthreads();
    const int row = r * 16 + g;
    const float inv0 = 1.f / (rsum[row] + rsum[64 + row]);
    const float inv1 = 1.f / (rsum[row + 8] + rsum[64 + row + 8]);

    // ---- store X (split bf16): this warp's 128 D cols ----
    const size_t r0 = (size_t)(b * SS + q0 + row) * DD;
    const size_t r1 = r0 + 8 * DD;
#pragma unroll
    for (int nt = 0; nt < 16; nt++) {
        int col = h * 128 + nt * 8 + 2 * t;
        float v0 = o[nt * 4 + 0] * inv0, v1 = o[nt * 4 + 1] * inv0;
        float v2 = o[nt * 4 + 2] * inv1, v3 = o[nt * 4 + 3] * inv1;
        __nv_bfloat16 h0, l0, h1, l1, h2, l2, h3, l3;
        splitb(v0, h0, l0); splitb(v1, h1, l1);
        splitb(v2, h2, l2); splitb(v3, h3, l3);
        *(uint32_t*)&g_Xh[r0 + col] = packb2(h0, h1);
        *(uint32_t*)&g_Xl[r0 + col] = packb2(l0, l1);
        *(uint32_t*)&g_Xh[r1 + col] = packb2(h2, h3);
        *(uint32_t*)&g_Xl[r1 + col] = packb2(l2, l3);
    }
}

// ---------------- launch ----------------
extern "C" void kernel_launch(void* const* d_in, const int* in_sizes, int n_in,
                              void* d_out, int out_size)
{
    const float* inp = (const float*)d_in[0];
    const float* wq  = (const float*)d_in[1];
    const float* bq  = (const float*)d_in[2];
    const float* wk  = (const float*)d_in[3];
    const float* bk  = (const float*)d_in[4];
    const float* wv  = (const float*)d_in[5];
    const float* bv  = (const float*)d_in[6];
    const float* wo  = (const float*)d_in[7];
    const float* bo  = (const float*)d_in[8];
    float* out = (float*)d_out;

    __half *Qp, *Kp, *Vp;
    __nv_bfloat16 *Xh, *Xl;
    cudaGetSymbolAddress((void**)&Qp, g_Q);
    cudaGetSymbolAddress((void**)&Kp, g_K);
    cudaGetSymbolAddress((void**)&Vp, g_Vt);
    cudaGetSymbolAddress((void**)&Xh, g_Xh);
    cudaGetSymbolAddress((void**)&Xl, g_Xl);

    cudaFuncSetAttribute(flash6_kernel,
                         cudaFuncAttributeMaxDynamicSharedMemorySize, F6_SMEM);
    cudaFuncSetAttribute(proj_fused,
                         cudaFuncAttributeMaxDynamicSharedMemorySize, PROJ_SMEM);

    // 1) weight transpose + split (q,k,v,o)
    prep_w<<<dim3(DD / 32, DD / 32, 4), 256>>>(wq, wk, wv, wo);

    // 2) fused QKV projection (1 wave of 128 CTAs)
    proj_fused<<<128, 256, PROJ_SMEM>>>(inp, nullptr, nullptr,
                                        bq, bk, bv, bo, Qp, Kp, Vp, nullptr, 0);

    // 3) attention: 64-row CTAs, 2 per SM
    flash6_kernel<<<dim3(SS / 64, BB), 256, F6_SMEM>>>();

    // 4) output projection
    proj_fused<<<128, 256, PROJ_SMEM>>>(nullptr, Xh, Xl,
                                        bq, bk, bv, bo, nullptr, nullptr, nullptr, out, 1);
}

// round 17
// speedup vs baseline: 1.3487x; 1.3487x over previous
#include <cuda_runtime.h>
#include <cuda_fp16.h>
#include <cuda_bf16.h>
#include <cstdint>

#define BB 4
#define SS 4096
#define DD 256
#define M_TOT (BB * SS)

// Scratch (device globals). Q pre-scaled by log2(e)/16; Vt is [b][d][s].
__device__ __half g_Q[M_TOT * DD];
__device__ __half g_K[M_TOT * DD];
__device__ __half g_Vt[M_TOT * DD];
__device__ __nv_bfloat16 g_WtH[4 * DD * DD], g_WtL[4 * DD * DD]; // W^T hi/lo, [n][k]

// ---------------- helpers ----------------
__device__ __forceinline__ uint32_t smem_u32(const void* p) {
    uint32_t a;
    asm("{ .reg .u64 t; cvta.to.shared.u64 t, %1; cvt.u32.u64 %0, t; }"
        : "=r"(a) : "l"(p));
    return a;
}
__device__ __forceinline__ uint32_t packh2(float a, float b) {
    __half2 v; v.x = __float2half(a); v.y = __float2half(b);
    return *reinterpret_cast<uint32_t*>(&v);
}
__device__ __forceinline__ uint32_t packb2(__nv_bfloat16 a, __nv_bfloat16 b) {
    __nv_bfloat162 v; v.x = a; v.y = b;
    return *reinterpret_cast<uint32_t*>(&v);
}
__device__ __forceinline__ void splitb(float x, __nv_bfloat16& h, __nv_bfloat16& l) {
    h = __float2bfloat16(x);
    l = __float2bfloat16(x - __bfloat162float(h));
}

#define LDSM4(d, addr) \
    asm volatile("ldmatrix.sync.aligned.m8n8.x4.shared.b16 {%0,%1,%2,%3}, [%4];" \
        : "=r"((d)[0]), "=r"((d)[1]), "=r"((d)[2]), "=r"((d)[3]) : "r"(addr))

#define MMAH(c, a, b0, b1) \
    asm volatile("mma.sync.aligned.m16n8k16.row.col.f32.f16.f16.f32 " \
        "{%0,%1,%2,%3}, {%4,%5,%6,%7}, {%8,%9}, {%0,%1,%2,%3};" \
        : "+f"((c)[0]), "+f"((c)[1]), "+f"((c)[2]), "+f"((c)[3]) \
        : "r"((a)[0]), "r"((a)[1]), "r"((a)[2]), "r"((a)[3]), "r"(b0), "r"(b1))

#define MMAB(c, a, b0, b1) \
    asm volatile("mma.sync.aligned.m16n8k16.row.col.f32.bf16.bf16.f32 " \
        "{%0,%1,%2,%3}, {%4,%5,%6,%7}, {%8,%9}, {%0,%1,%2,%3};" \
        : "+f"((c)[0]), "+f"((c)[1]), "+f"((c)[2]), "+f"((c)[3]) \
        : "r"((a)[0]), "r"((a)[1]), "r"((a)[2]), "r"((a)[3]), "r"(b0), "r"(b1))

#define CP_ASYNC16(dst, src) \
    asm volatile("cp.async.cg.shared.global [%0], [%1], 16;" \
                 :: "r"(dst), "l"(src) : "memory")
#define CP_COMMIT  asm volatile("cp.async.commit_group;" ::: "memory")
#define CP_WAIT0   asm volatile("cp.async.wait_group 0;" ::: "memory")

// ---------------- weight prep: W[k][n] f32 -> Wt[n][k] bf16 hi/lo ----------------
__global__ __launch_bounds__(256) void prep_w(
    const float* __restrict__ w0, const float* __restrict__ w1,
    const float* __restrict__ w2, const float* __restrict__ w3)
{
    const float* W = (blockIdx.z == 0) ? w0 : (blockIdx.z == 1) ? w1
                   : (blockIdx.z == 2) ? w2 : w3;
    __nv_bfloat16* TH = g_WtH + blockIdx.z * DD * DD;
    __nv_bfloat16* TL = g_WtL + blockIdx.z * DD * DD;

    __shared__ float t[32][33];
    const int tx = threadIdx.x & 31;
    const int ty = threadIdx.x >> 5;
    const int k0 = blockIdx.x * 32;
    const int n0 = blockIdx.y * 32;
#pragma unroll
    for (int i = 0; i < 4; i++)
        t[ty + 8 * i][tx] = W[(size_t)(k0 + ty + 8 * i) * DD + n0 + tx];
    __syncthreads();
#pragma unroll
    for (int i = 0; i < 4; i++) {
        float v = t[tx][ty + 8 * i];
        __nv_bfloat16 h, l; splitb(v, h, l);
        size_t idx = (size_t)(n0 + ty + 8 * i) * DD + k0 + tx;
        TH[idx] = h;
        TL[idx] = l;
    }
}

// ---------------- fused QKV projection (split bf16, 3-MMA), grid = 128 ----------
// A = inp f32 (lda 768); weights q,k,v (24 col-tiles of 32).
// Epilogues: Q fp16 * log2e/16, K fp16, V fp16 transposed [b][d][s].
#define PP 528
#define A_H   0u
#define A_L   67584u
#define WBUF0 135168u
#define WBUF1 168960u
#define WLO   16896u
#define VT_OFF 202752u
#define PROJ_SMEM 219648

__global__ __launch_bounds__(256, 1) void proj_fused(
    const float* __restrict__ Af,
    const float* __restrict__ biasq, const float* __restrict__ biask,
    const float* __restrict__ biasv,
    __half* __restrict__ Qo, __half* __restrict__ Ko, __half* __restrict__ Vo)
{
    extern __shared__ __align__(16) char sm[];
    const uint32_t sb = smem_u32(sm);
    const int tid  = threadIdx.x;
    const int wid  = tid >> 5;
    const int lane = tid & 31;
    const int row0 = blockIdx.x * 128;

    {
        const __nv_bfloat16* TH = g_WtH;
        const __nv_bfloat16* TL = g_WtL;
        const uint32_t wb = sb + WBUF0;
#pragma unroll
        for (int p = 0; p < 4; p++) {
            int idx = tid + p * 256;
            int rr = idx >> 5, c = idx & 31;
            CP_ASYNC16(wb + rr * PP + c * 16,       TH + (size_t)rr * DD + c * 8);
            CP_ASYNC16(wb + WLO + rr * PP + c * 16, TL + (size_t)rr * DD + c * 8);
        }
        CP_COMMIT;
    }

    const int lr  = lane & 7;
    const int lt2 = (lane >> 3) & 1;
    const int lt4 = lane >> 4;
    const uint32_t a_h = sb + A_H + (uint32_t)(wid * 16 + lt2 * 8 + lr) * PP + lt4 * 16;
    const uint32_t a_l = a_h + (A_L - A_H);
    const uint32_t bw_lane = (uint32_t)(lt4 * 8 + lr) * PP + lt2 * 16;
    const int g = lane >> 2, t = lane & 3;

#pragma unroll 1
    for (int tt = 0; tt < 24; tt++) {
        const int wt   = tt >> 3;
        const int col0 = (tt & 7) * 32;

        if ((tt & 7) == 0) {
            __syncthreads();
            const int aoff = wt * 256;
#pragma unroll
            for (int p = 0; p < 32; p++) {
                int idx = tid + p * 256;
                int rr = idx >> 6, c4 = idx & 63;
                float4 v = *(const float4*)&Af[(size_t)(row0 + rr) * 768 + aoff + c4 * 4];
                __nv_bfloat16 h0, l0, h1, l1, h2, l2, h3, l3;
                splitb(v.x, h0, l0); splitb(v.y, h1, l1);
                splitb(v.z, h2, l2); splitb(v.w, h3, l3);
                *(uint2*)(sm + A_H + rr * PP + c4 * 8) =
                    make_uint2(packb2(h0, h1), packb2(h2, h3));
                *(uint2*)(sm + A_L + rr * PP + c4 * 8) =
                    make_uint2(packb2(l0, l1), packb2(l2, l3));
            }
        }

        CP_WAIT0;
        __syncthreads();

        if (tt + 1 < 24) {
            const int wt1 = (tt + 1) >> 3;
            const int co1 = ((tt + 1) & 7) * 32;
            const __nv_bfloat16* TH = g_WtH + (size_t)wt1 * DD * DD + (size_t)co1 * DD;
            const __nv_bfloat16* TL = g_WtL + (size_t)wt1 * DD * DD + (size_t)co1 * DD;
            const uint32_t wb = sb + (((tt + 1) & 1) ? WBUF1 : WBUF0);
#pragma unroll
            for (int p = 0; p < 4; p++) {
                int idx = tid + p * 256;
                int rr = idx >> 5, c = idx & 31;
                CP_ASYNC16(wb + rr * PP + c * 16,       TH + (size_t)rr * DD + c * 8);
                CP_ASYNC16(wb + WLO + rr * PP + c * 16, TL + (size_t)rr * DD + c * 8);
            }
            CP_COMMIT;
        }

        const uint32_t b_h = sb + ((tt & 1) ? WBUF1 : WBUF0) + bw_lane;
        const uint32_t b_l = b_h + WLO;
        float c_[4][4];
#pragma unroll
        for (int i = 0; i < 4; i++)
#pragma unroll
            for (int j = 0; j < 4; j++) c_[i][j] = 0.f;

#pragma unroll
        for (int ks = 0; ks < 16; ks++) {
            uint32_t ah[4], al[4];
            LDSM4(ah, a_h + ks * 32);
            LDSM4(al, a_l + ks * 32);
#pragma unroll
            for (int j2 = 0; j2 < 2; j2++) {
                uint32_t bh[4], bl[4];
                LDSM4(bh, b_h + j2 * (16 * PP) + ks * 32);
                LDSM4(bl, b_l + j2 * (16 * PP) + ks * 32);
                MMAB(c_[2 * j2],     ah, bh[0], bh[1]);
                MMAB(c_[2 * j2],     al, bh[0], bh[1]);
                MMAB(c_[2 * j2],     ah, bl[0], bl[1]);
                MMAB(c_[2 * j2 + 1], ah, bh[2], bh[3]);
                MMAB(c_[2 * j2 + 1], al, bh[2], bh[3]);
                MMAB(c_[2 * j2 + 1], ah, bl[2], bl[3]);
            }
        }

        if (wt == 0 || wt == 1) {
            __half* outp = (wt == 0) ? Qo : Ko;
            const float* bp = (wt == 0) ? biasq : biask;
            const float scale = (wt == 0) ? 0.0625f * 1.44269504088896f : 1.0f;
            const int r0 = row0 + wid * 16 + g;
#pragma unroll
            for (int nt = 0; nt < 4; nt++) {
                int col = col0 + nt * 8 + 2 * t;
                float b0 = bp[col], b1 = bp[col + 1];
                *(uint32_t*)&outp[(size_t)r0 * DD + col] =
                    packh2((c_[nt][0] + b0) * scale, (c_[nt][1] + b1) * scale);
                *(uint32_t*)&outp[(size_t)(r0 + 8) * DD + col] =
                    packh2((c_[nt][2] + b0) * scale, (c_[nt][3] + b1) * scale);
            }
        } else {
            __syncthreads();
            float* sh = (float*)(sm + VT_OFF);
            const int rl = wid * 16 + g;
#pragma unroll
            for (int nt = 0; nt < 4; nt++) {
                int cl = nt * 8 + 2 * t;
                float b0 = biasv[col0 + cl], b1 = biasv[col0 + cl + 1];
                sh[rl * 33 + cl]           = c_[nt][0] + b0;
                sh[rl * 33 + cl + 1]       = c_[nt][1] + b1;
                sh[(rl + 8) * 33 + cl]     = c_[nt][2] + b0;
                sh[(rl + 8) * 33 + cl + 1] = c_[nt][3] + b1;
            }
            __syncthreads();
            const int sl = tid & 63;
            const int d0 = tid >> 6;
            const int b_ = row0 >> 12;
            const int s0 = row0 & 4095;
            __half* Vb = Vo + (size_t)b_ * DD * SS;
#pragma unroll
            for (int dd = 0; dd < 8; dd++) {
                int d = d0 + dd * 4;
                *(uint32_t*)&Vb[(size_t)(col0 + d) * SS + s0 + 2 * sl] =
                    packh2(sh[(2 * sl) * 33 + d], sh[(2 * sl + 1) * 33 + d]);
            }
        }
    }
}

// ---------------- flash attention + fused output projection -----------------------
// Mainloop = R14 flash4 (validated ~231-233us). Epilogue: X (regs) -> split bf16
// smem -> 8-tile GEMM vs Wo (cp.async double buffered) -> out f32 + bias.
#define QPITCH 528
#define VPITCH 144
#define Q_OFF  0u
#define BUF0   67584u
#define BUFSZ  70656u
#define KOFF   0u
#define VOFF   33792u
// epilogue reuse: X_H @ 0 (Q area, 67584), X_L @ 67584 (BUF0 area),
// W double buffers @ 138240 / 172032 (BUF1 area; last KV tile lives in BUF1 so
// we sync before the first W prefetch).
#define XE_H   0u
#define XE_L   67584u
#define FWB0   138240u
#define FWB1   172032u
#define FLASH_SMEM 208896

__global__ __launch_bounds__(256) void flash4_kernel(
    const float* __restrict__ biaso, float* __restrict__ out)
{
    extern __shared__ __align__(16) char sm[];
    const uint32_t sb = smem_u32(sm);

    const int tid  = threadIdx.x;
    const int wid  = tid >> 5;
    const int lane = tid & 31;
    const int b    = blockIdx.y;
    const int q0   = blockIdx.x * 128;

    const __half* Qg  = g_Q  + (size_t)(b * SS + q0) * DD;
    const __half* Kg  = g_K  + (size_t)b * SS * DD;
    const __half* Vtg = g_Vt + (size_t)b * DD * SS;

#pragma unroll
    for (int p = 0; p < 16; p++) {
        int idx = tid + p * 256;
        int r  = idx >> 5;
        int c  = idx & 31;
        *(uint4*)(sm + Q_OFF + r * QPITCH + c * 16) =
            *(const uint4*)(Qg + (size_t)r * DD + c * 8);
    }
    {
        const uint32_t kb = sb + BUF0 + KOFF;
        const uint32_t vb = sb + BUF0 + VOFF;
#pragma unroll
        for (int p = 0; p < 8; p++) {
            int idx = tid + p * 256;
            int r = idx >> 5, c = idx & 31;
            CP_ASYNC16(kb + r * QPITCH + c * 16, Kg + (size_t)r * DD + c * 8);
        }
#pragma unroll
        for (int p = 0; p < 8; p++) {
            int idx = tid + p * 256;
            int d = idx >> 3, c = idx & 7;
            CP_ASYNC16(vb + d * VPITCH + c * 16, Vtg + (size_t)d * SS + c * 8);
        }
        CP_COMMIT;
    }

    const int lr  = lane & 7;
    const int lt2 = (lane >> 3) & 1;
    const int lt4 = lane >> 4;
    const uint32_t a_q = sb + Q_OFF +
        (uint32_t)(wid * 16 + lt2 * 8 + lr) * QPITCH + lt4 * 16;
    const uint32_t bk_lane = (uint32_t)(lt4 * 8 + lr) * QPITCH + lt2 * 16;
    const uint32_t bv_lane = (uint32_t)(lt4 * 8 + lr) * VPITCH + lt2 * 16;

    float o[128];
#pragma unroll
    for (int i = 0; i < 128; i++) o[i] = 0.f;
    float rs0 = 0.f, rs1 = 0.f;

#pragma unroll 1
    for (int kt = 0; kt < SS / 64; kt++) {
        const uint32_t base = sb + BUF0 + (uint32_t)(kt & 1) * BUFSZ;
        CP_WAIT0;
        __syncthreads();

        if (kt < SS / 64 - 1) {
            const uint32_t kb = sb + BUF0 + (uint32_t)((kt + 1) & 1) * BUFSZ + KOFF;
            const uint32_t vb = sb + BUF0 + (uint32_t)((kt + 1) & 1) * BUFSZ + VOFF;
            const __half* Kn = Kg  + (size_t)(kt + 1) * 64 * DD;
            const __half* Vn = Vtg + (size_t)(kt + 1) * 64;
#pragma unroll
            for (int p = 0; p < 8; p++) {
                int idx = tid + p * 256;
                int r = idx >> 5, c = idx & 31;
                CP_ASYNC16(kb + r * QPITCH + c * 16, Kn + (size_t)r * DD + c * 8);
            }
#pragma unroll
            for (int p = 0; p < 8; p++) {
                int idx = tid + p * 256;
                int d = idx >> 3, c = idx & 7;
                CP_ASYNC16(vb + d * VPITCH + c * 16, Vn + (size_t)d * SS + c * 8);
            }
            CP_COMMIT;
        }

        // ---- S = Q K^T : per warp 16 rows x 64 cols, K=256 ----
        const uint32_t b_k = base + KOFF + bk_lane;
        float s[8][4];
#pragma unroll
        for (int i = 0; i < 8; i++)
#pragma unroll
            for (int j = 0; j < 4; j++) s[i][j] = 0.f;

#pragma unroll
        for (int ks = 0; ks < 16; ks++) {
            uint32_t a[4];
            LDSM4(a, a_q + ks * 32);
#pragma unroll
            for (int j2 = 0; j2 < 4; j2++) {
                uint32_t bb[4];
                LDSM4(bb, b_k + j2 * (16 * QPITCH) + ks * 32);
                MMAH(s[2 * j2],     a, bb[0], bb[1]);
                MMAH(s[2 * j2 + 1], a, bb[2], bb[3]);
            }
        }

        // ---- chunked exp2 -> PV (16 kv-cols per chunk) ----
        const uint32_t b_v = base + VOFF + bv_lane;
#pragma unroll
        for (int kk = 0; kk < 4; kk++) {
            float p0 = exp2f(s[2 * kk][0]);
            float p1 = exp2f(s[2 * kk][1]);
            float p2 = exp2f(s[2 * kk][2]);
            float p3 = exp2f(s[2 * kk][3]);
            float q0r = exp2f(s[2 * kk + 1][0]);
            float q1r = exp2f(s[2 * kk + 1][1]);
            float q2r = exp2f(s[2 * kk + 1][2]);
            float q3r = exp2f(s[2 * kk + 1][3]);
            rs0 += (p0 + p1) + (q0r + q1r);
            rs1 += (p2 + p3) + (q2r + q3r);
            uint32_t pa[4];
            pa[0] = packh2(p0, p1);
            pa[1] = packh2(p2, p3);
            pa[2] = packh2(q0r, q1r);
            pa[3] = packh2(q2r, q3r);
#pragma unroll
            for (int jj = 0; jj < 16; jj++) {
                uint32_t vv[4];
                LDSM4(vv, b_v + jj * (16 * VPITCH) + kk * 32);
                MMAH(o + (2 * jj) * 4,     pa, vv[0], vv[1]);
                MMAH(o + (2 * jj + 1) * 4, pa, vv[2], vv[3]);
            }
        }
    }

    // ---- rowsums + normalize ----
    rs0 += __shfl_xor_sync(0xffffffffu, rs0, 1);
    rs0 += __shfl_xor_sync(0xffffffffu, rs0, 2);
    rs1 += __shfl_xor_sync(0xffffffffu, rs1, 1);
    rs1 += __shfl_xor_sync(0xffffffffu, rs1, 2);
    const float inv0 = 1.f / rs0;
    const float inv1 = 1.f / rs1;

    // ---- stage X (split bf16) into smem (Q + BUF0 areas; BUF1 untouched) ----
    const int g = lane >> 2, t = lane & 3;
#pragma unroll
    for (int nt = 0; nt < 32; nt++) {
        int col = nt * 8 + 2 * t;
        float v0 = o[nt * 4 + 0] * inv0, v1 = o[nt * 4 + 1] * inv0;
        float v2 = o[nt * 4 + 2] * inv1, v3 = o[nt * 4 + 3] * inv1;
        __nv_bfloat16 h0, l0, h1, l1, h2, l2, h3, l3;
        splitb(v0, h0, l0); splitb(v1, h1, l1);
        splitb(v2, h2, l2); splitb(v3, h3, l3);
        uint32_t r0off = (uint32_t)(wid * 16 + g) * PP + (uint32_t)col * 2;
        uint32_t r1off = r0off + 8 * PP;
        *(uint32_t*)(sm + XE_H + r0off) = packb2(h0, h1);
        *(uint32_t*)(sm + XE_L + r0off) = packb2(l0, l1);
        *(uint32_t*)(sm + XE_H + r1off) = packb2(h2, h3);
        *(uint32_t*)(sm + XE_L + r1off) = packb2(l2, l3);
    }
    __syncthreads();   // X staged; last KV tile reads done -> BUF1 reusable for W

    // ---- fused output projection: 8 col-tiles of Wo (widx 3) ----
    const __nv_bfloat16* WoH = g_WtH + 3 * DD * DD;
    const __nv_bfloat16* WoL = g_WtL + 3 * DD * DD;
    {
        const uint32_t wb = sb + FWB0;
#pragma unroll
        for (int p = 0; p < 4; p++) {
            int idx = tid + p * 256;
            int rr = idx >> 5, c = idx & 31;
            CP_ASYNC16(wb + rr * PP + c * 16,       WoH + (size_t)rr * DD + c * 8);
            CP_ASYNC16(wb + WLO + rr * PP + c * 16, WoL + (size_t)rr * DD + c * 8);
        }
        CP_COMMIT;
    }

    const uint32_t a_h = sb + XE_H + (uint32_t)(wid * 16 + lt2 * 8 + lr) * PP + lt4 * 16;
    const uint32_t a_l = a_h + (XE_L - XE_H);
    const uint32_t bw_lane = (uint32_t)(lt4 * 8 + lr) * PP + lt2 * 16;

#pragma unroll 1
    for (int tt = 0; tt < 8; tt++) {
        const int col0 = tt * 32;
        CP_WAIT0;
        __syncthreads();

        if (tt + 1 < 8) {
            const int co1 = (tt + 1) * 32;
            const uint32_t wb = sb + (((tt + 1) & 1) ? FWB1 : FWB0);
#pragma unroll
            for (int p = 0; p < 4; p++) {
                int idx = tid + p * 256;
                int rr = idx >> 5, c = idx & 31;
                CP_ASYNC16(wb + rr * PP + c * 16,
                           WoH + (size_t)(co1 + rr) * DD + c * 8);
                CP_ASYNC16(wb + WLO + rr * PP + c * 16,
                           WoL + (size_t)(co1 + rr) * DD + c * 8);
            }
            CP_COMMIT;
        }

        const uint32_t b_h = sb + ((tt & 1) ? FWB1 : FWB0) + bw_lane;
        const uint32_t b_l = b_h + WLO;
        float c_[4][4];
#pragma unroll
        for (int i = 0; i < 4; i++)
#pragma unroll
            for (int j = 0; j < 4; j++) c_[i][j] = 0.f;

#pragma unroll
        for (int ks = 0; ks < 16; ks++) {
            uint32_t ah[4], al[4];
            LDSM4(ah, a_h + ks * 32);
            LDSM4(al, a_l + ks * 32);
#pragma unroll
            for (int j2 = 0; j2 < 2; j2++) {
                uint32_t bh[4], bl[4];
                LDSM4(bh, b_h + j2 * (16 * PP) + ks * 32);
                LDSM4(bl, b_l + j2 * (16 * PP) + ks * 32);
                MMAB(c_[2 * j2],     ah, bh[0], bh[1]);
                MMAB(c_[2 * j2],     al, bh[0], bh[1]);
                MMAB(c_[2 * j2],     ah, bl[0], bl[1]);
                MMAB(c_[2 * j2 + 1], ah, bh[2], bh[3]);
                MMAB(c_[2 * j2 + 1], al, bh[2], bh[3]);
                MMAB(c_[2 * j2 + 1], ah, bl[2], bl[3]);
            }
        }

        const int r0 = b * SS + q0 + wid * 16 + g;
#pragma unroll
        for (int nt = 0; nt < 4; nt++) {
            int col = col0 + nt * 8 + 2 * t;
            float b0 = biaso[col], b1 = biaso[col + 1];
            *(float2*)&out[(size_t)r0 * DD + col] =
                make_float2(c_[nt][0] + b0, c_[nt][1] + b1);
            *(float2*)&out[(size_t)(r0 + 8) * DD + col] =
                make_float2(c_[nt][2] + b0, c_[nt][3] + b1);
        }
    }
}

// ---------------- launch ----------------
extern "C" void kernel_launch(void* const* d_in, const int* in_sizes, int n_in,
                              void* d_out, int out_size)
{
    const float* inp = (const float*)d_in[0];
    const float* wq  = (const float*)d_in[1];
    const float* bq  = (const float*)d_in[2];
    const float* wk  = (const float*)d_in[3];
    const float* bk  = (const float*)d_in[4];
    const float* wv  = (const float*)d_in[5];
    const float* bv  = (const float*)d_in[6];
    const float* wo  = (const float*)d_in[7];
    const float* bo  = (const float*)d_in[8];
    float* out = (float*)d_out;

    __half *Qp, *Kp, *Vp;
    cudaGetSymbolAddress((void**)&Qp, g_Q);
    cudaGetSymbolAddress((void**)&Kp, g_K);
    cudaGetSymbolAddress((void**)&Vp, g_Vt);

    cudaFuncSetAttribute(flash4_kernel,
                         cudaFuncAttributeMaxDynamicSharedMemorySize, FLASH_SMEM);
    cudaFuncSetAttribute(proj_fused,
                         cudaFuncAttributeMaxDynamicSharedMemorySize, PROJ_SMEM);

    // 1) weight transpose + split (q,k,v,o)
    prep_w<<<dim3(DD / 32, DD / 32, 4), 256>>>(wq, wk, wv, wo);

    // 2) fused QKV projection (1 wave of 128 CTAs)
    proj_fused<<<128, 256, PROJ_SMEM>>>(inp, bq, bk, bv, Qp, Kp, Vp);

    // 3) attention + fused output projection (3 launches total)
    flash4_kernel<<<dim3(SS / 128, BB), 256, FLASH_SMEM>>>(bo, out);
}